// round 1
// baseline (speedup 1.0000x reference)
#include <cuda_runtime.h>
#include <math.h>

#define BN 128
#define SN 1024
#define DN 256
#define D4 64
#define NROWS (BN * SN)          // 131072
#define NBLK 1024                // blocks for the two big row passes
#define ROWS_PER_BLK (NROWS / NBLK)     // 128
#define ROWS_PER_WARP (ROWS_PER_BLK / 8) // 16

// ---------------- scratch (device globals; no allocation) ----------------
__device__ float g_cb[BN * DN];        // per-batch centroids
__device__ float g_mu[DN];             // global centroid
__device__ float g_psum[NBLK * DN];    // per-block column sums of w
__device__ float g_psumsq[NBLK * DN];  // per-block column sums of w^2
__device__ float g_psum2[8 * DN];
__device__ float g_psumsq2[8 * DN];
__device__ float g_scale[DN];          // gamma / sqrt(var + eps)

// ---------------- helpers ----------------
__device__ __forceinline__ float wsum(float v) {
#pragma unroll
    for (int o = 16; o; o >>= 1) v += __shfl_xor_sync(0xffffffffu, v, o);
    return v;
}
__device__ __forceinline__ float4 f4z() { return make_float4(0.f, 0.f, 0.f, 0.f); }
__device__ __forceinline__ float4 f4add(float4 a, float4 b) {
    return make_float4(a.x + b.x, a.y + b.y, a.z + b.z, a.w + b.w);
}
__device__ __forceinline__ float4 f4scale(float4 a, float s) {
    return make_float4(a.x * s, a.y * s, a.z * s, a.w * s);
}
__device__ __forceinline__ float dot4(float4 a, float4 b) {
    return a.x * b.x + a.y * b.y + a.z * b.z + a.w * b.w;
}
// w_d = f*(x_d - alpha*mu_d) - coef*mu_d  (delta for d==0 handled by caller)
__device__ __forceinline__ float4 wcomp(float4 xv, float4 muv, float alpha, float f, float coef) {
    float4 r;
    r.x = f * fmaf(-alpha, muv.x, xv.x) - coef * muv.x;
    r.y = f * fmaf(-alpha, muv.y, xv.y) - coef * muv.y;
    r.z = f * fmaf(-alpha, muv.z, xv.z) - coef * muv.z;
    r.w = f * fmaf(-alpha, muv.w, xv.w) - coef * muv.w;
    return r;
}
__device__ __forceinline__ float4 f4mul(float4 a, float4 b) {
    return make_float4(a.x * b.x, a.y * b.y, a.z * b.z, a.w * b.w);
}
__device__ __forceinline__ float4 f4fma(float4 a, float s, float4 b) {
    // a*s + b
    return make_float4(fmaf(a.x, s, b.x), fmaf(a.y, s, b.y), fmaf(a.z, s, b.z), fmaf(a.w, s, b.w));
}

// ---------------- kernel 1: per-batch Lorentz centroid ----------------
// grid 128, block 256. Sum over S, normalize on the hyperboloid -> g_cb[b][d].
__global__ void k_batch_centroid(const float* __restrict__ x) {
    int b = blockIdx.x;
    int w = threadIdx.x >> 5, l = threadIdx.x & 31;
    const float4* xp = (const float4*)(x + (size_t)b * SN * DN);
    float4 a0 = f4z(), a1 = f4z();
#pragma unroll 4
    for (int s = w; s < SN; s += 8) {
        const float4* row = xp + (size_t)s * D4;
        a0 = f4add(a0, row[l]);
        a1 = f4add(a1, row[l + 32]);
    }
    __shared__ float4 s0[8][32], s1[8][32];
    __shared__ float spart[2];
    s0[w][l] = a0;
    s1[w][l] = a1;
    __syncthreads();
    if (w < 2) {
        float4 t = f4z();
#pragma unroll
        for (int i = 0; i < 8; i++) t = f4add(t, (w == 0) ? s0[i][l] : s1[i][l]);
        float4 avg = f4scale(t, 1.0f / (float)SN);
        float part;
        if (w == 0 && l == 0)
            part = avg.x * avg.x - (avg.y * avg.y + avg.z * avg.z + avg.w * avg.w);
        else
            part = -dot4(avg, avg);
        part = wsum(part);
        if (l == 0) spart[w] = part;
        // stash avg (each warp writes only its own slot row 0 of its own array)
        if (w == 0) s0[0][l] = avg; else s1[0][l] = avg;
    }
    __syncthreads();
    if (w < 2) {
        float nrm = spart[0] + spart[1];
        float rden = rsqrtf(fmaxf(fabsf(nrm), 1e-8f));
        float4 avg = (w == 0) ? s0[0][l] : s1[0][l];
        ((float4*)g_cb)[b * D4 + w * 32 + l] = f4scale(avg, rden);
    }
}

// ---------------- kernel 2: global centroid over batches ----------------
// 1 block, 1024 threads: q=tid>>8 sums 32 batches for column d=tid&255.
__global__ void k_global_centroid() {
    int tid = threadIdx.x;
    int q = tid >> 8, d = tid & 255;
    __shared__ float sm[4][DN];
    __shared__ float sm2[8];
    __shared__ float srden;
    float s = 0.f;
#pragma unroll 8
    for (int b = q * 32; b < q * 32 + 32; b++) s += g_cb[b * DN + d];
    sm[q][d] = s;
    __syncthreads();
    if (tid < DN) {
        float tot = sm[0][d] + sm[1][d] + sm[2][d] + sm[3][d];
        float avg = tot * (1.0f / (float)BN);
        sm[0][d] = avg;
        float part = (d == 0) ? avg * avg : -avg * avg;
        part = wsum(part);
        if ((tid & 31) == 0) sm2[tid >> 5] = part;
    }
    __syncthreads();
    if (tid == 0) {
        float nrm = 0.f;
#pragma unroll
        for (int i = 0; i < 8; i++) nrm += sm2[i];
        srden = rsqrtf(fmaxf(fabsf(nrm), 1e-8f));
    }
    __syncthreads();
    if (tid < DN) g_mu[d] = sm[0][d] * srden;
}

// ---------------- kernel 3: tangent stats pass ----------------
// grid NBLK, block 256. Warp-per-row, shuffle reductions only.
__global__ void k_stats(const float* __restrict__ x) {
    int w = threadIdx.x >> 5, l = threadIdx.x & 31;
    const float4* mu4 = (const float4*)g_mu;
    float4 mu_a = mu4[l], mu_b = mu4[l + 32];
    float mu0 = g_mu[0];
    float inv1 = 1.0f / (1.0f + mu0);
    int rbase = blockIdx.x * ROWS_PER_BLK + w;
    const float4* xp = (const float4*)x;

    float4 s1a = f4z(), s1b = f4z(), s2a = f4z(), s2b = f4z();
    const float4* row0 = xp + (size_t)rbase * D4;
    float4 xa = row0[l], xb = row0[l + 32];
#pragma unroll
    for (int i = 0; i < ROWS_PER_WARP; i++) {
        float4 na = f4z(), nb = f4z();
        if (i + 1 < ROWS_PER_WARP) {
            const float4* nr = xp + (size_t)(rbase + (i + 1) * 8) * D4;
            na = nr[l];
            nb = nr[l + 32];
        }
        // alpha = -<mu, x>_L
        float part = -dot4(mu_b, xb);
        part += (l == 0)
            ? (mu0 * xa.x - (mu_a.y * xa.y + mu_a.z * xa.z + mu_a.w * xa.w))
            : -dot4(mu_a, xa);
        float alpha = wsum(part);
        float x0 = __shfl_sync(0xffffffffu, xa.x, 0);
        alpha = fmaxf(alpha, 1.0f + 1e-7f);
        float f = acoshf(alpha) * rsqrtf(fmaf(alpha, alpha, -1.0f));
        float t0 = f * fmaf(-alpha, mu0, x0);
        float coef = t0 * inv1;
        float4 wa = wcomp(xa, mu_a, alpha, f, coef);
        float4 wb = wcomp(xb, mu_b, alpha, f, coef);
        if (l == 0) wa.x -= coef;  // add_origin delta on component 0
        s1a = f4add(s1a, wa);
        s1b = f4add(s1b, wb);
        s2a = f4add(s2a, f4mul(wa, wa));
        s2b = f4add(s2b, f4mul(wb, wb));
        xa = na;
        xb = nb;
    }
    // combine 8 warps -> per-block column partials
    __shared__ float4 sbA[8][32], sbB[8][32];
    sbA[w][l] = s1a;
    sbB[w][l] = s1b;
    __syncthreads();
    if (w == 0) {
        float4 t = f4z();
#pragma unroll
        for (int i = 0; i < 8; i++) t = f4add(t, sbA[i][l]);
        ((float4*)g_psum)[blockIdx.x * D4 + l] = t;
    }
    if (w == 1) {
        float4 t = f4z();
#pragma unroll
        for (int i = 0; i < 8; i++) t = f4add(t, sbB[i][l]);
        ((float4*)g_psum)[blockIdx.x * D4 + 32 + l] = t;
    }
    __syncthreads();
    sbA[w][l] = s2a;
    sbB[w][l] = s2b;
    __syncthreads();
    if (w == 0) {
        float4 t = f4z();
#pragma unroll
        for (int i = 0; i < 8; i++) t = f4add(t, sbA[i][l]);
        ((float4*)g_psumsq)[blockIdx.x * D4 + l] = t;
    }
    if (w == 1) {
        float4 t = f4z();
#pragma unroll
        for (int i = 0; i < 8; i++) t = f4add(t, sbB[i][l]);
        ((float4*)g_psumsq)[blockIdx.x * D4 + 32 + l] = t;
    }
}

// ---------------- kernel 3b: reduce 1024 partials -> 8 ----------------
__global__ void k_reduce_partials() {
    int j = blockIdx.x, d = threadIdx.x;
    float s = 0.f, s2 = 0.f;
    int base = j * (NBLK / 8);
#pragma unroll 8
    for (int i = 0; i < NBLK / 8; i++) {
        s += g_psum[(size_t)(base + i) * DN + d];
        s2 += g_psumsq[(size_t)(base + i) * DN + d];
    }
    g_psum2[j * DN + d] = s;
    g_psumsq2[j * DN + d] = s2;
}

// ---------------- kernel 4: final variance -> scale ----------------
__global__ void k_scale_kernel(const float* __restrict__ gamma) {
    int d = threadIdx.x;
    float s = 0.f, s2 = 0.f;
#pragma unroll
    for (int j = 0; j < 8; j++) {
        s += g_psum2[j * DN + d];
        s2 += g_psumsq2[j * DN + d];
    }
    float invN = 1.0f / (float)NROWS;
    float mean = s * invN;
    float var = fmaf(-mean, mean, s2 * invN);
    var = fmaxf(var, 0.0f);
    g_scale[d] = gamma[0] * rsqrtf(var + 1e-5f);
}

// ---------------- kernel 5: output pass ----------------
// grid NBLK, block 256. Recompute w, scale, transp0(beta), expmap(beta).
__global__ void k_output(const float* __restrict__ x, const float* __restrict__ beta,
                         float* __restrict__ out) {
    int w = threadIdx.x >> 5, l = threadIdx.x & 31;
    const float4* mu4 = (const float4*)g_mu;
    const float4* sc4 = (const float4*)g_scale;
    const float4* be4 = (const float4*)beta;
    float4 mu_a = mu4[l], mu_b = mu4[l + 32];
    float4 sc_a = sc4[l], sc_b = sc4[l + 32];
    float4 be_a = be4[l], be_b = be4[l + 32];
    float mu0 = g_mu[0];
    float inv1 = 1.0f / (1.0f + mu0);
    float beta0 = beta[0];
    float inv1b = 1.0f / (1.0f + beta0);
    int rbase = blockIdx.x * ROWS_PER_BLK + w;
    const float4* xp = (const float4*)x;
    float4* op = (float4*)out;

    const float4* row0 = xp + (size_t)rbase * D4;
    float4 xa = row0[l], xb = row0[l + 32];
#pragma unroll
    for (int i = 0; i < ROWS_PER_WARP; i++) {
        int r = rbase + i * 8;
        float4 na = f4z(), nb = f4z();
        if (i + 1 < ROWS_PER_WARP) {
            const float4* nr = xp + (size_t)(r + 8) * D4;
            na = nr[l];
            nb = nr[l + 32];
        }
        // ---- alpha ----
        float part = -dot4(mu_b, xb);
        part += (l == 0)
            ? (mu0 * xa.x - (mu_a.y * xa.y + mu_a.z * xa.z + mu_a.w * xa.w))
            : -dot4(mu_a, xa);
        float alpha = wsum(part);
        float x0 = __shfl_sync(0xffffffffu, xa.x, 0);
        alpha = fmaxf(alpha, 1.0f + 1e-7f);
        float f = acoshf(alpha) * rsqrtf(fmaf(alpha, alpha, -1.0f));
        float t0 = f * fmaf(-alpha, mu0, x0);
        float coef = t0 * inv1;
        float4 wa = wcomp(xa, mu_a, alpha, f, coef);
        float4 wb = wcomp(xb, mu_b, alpha, f, coef);
        if (l == 0) wa.x -= coef;
        // ---- scale ----
        float4 va = f4mul(wa, sc_a);
        float4 vb = f4mul(wb, sc_b);
        // ---- transp0(beta, v): coef2 = <beta,v>_L / (1+beta0) ----
        float p2 = dot4(be_b, vb);
        p2 += (l == 0)
            ? (-beta0 * va.x + be_a.y * va.y + be_a.z * va.z + be_a.w * va.w)
            : dot4(be_a, va);
        float dotb = wsum(p2);
        float c2 = dotb * inv1b;
        float4 ya = f4fma(be_a, c2, va);
        float4 yb = f4fma(be_b, c2, vb);
        if (l == 0) ya.x += c2;  // add_origin delta
        // ---- expmap(beta, y): n = sqrt(clip(<y,y>_L, 1e-7)) ----
        float p3 = dot4(yb, yb);
        p3 += (l == 0)
            ? (-ya.x * ya.x + ya.y * ya.y + ya.z * ya.z + ya.w * ya.w)
            : dot4(ya, ya);
        float nrm = wsum(p3);
        float n = sqrtf(fmaxf(nrm, 1e-7f));
        float ch = coshf(n);
        float sn = sinhf(n) / n;
        float4 oa = f4fma(be_a, ch, f4scale(ya, sn));
        float4 ob = f4fma(be_b, ch, f4scale(yb, sn));
        op[(size_t)r * D4 + l] = oa;
        op[(size_t)r * D4 + 32 + l] = ob;
        xa = na;
        xb = nb;
    }
}

// ---------------- launcher ----------------
extern "C" void kernel_launch(void* const* d_in, const int* in_sizes, int n_in,
                              void* d_out, int out_size) {
    const float* x = (const float*)d_in[0];      // [B,S,D] f32
    const float* beta = (const float*)d_in[1];   // [D] f32
    const float* gamma = (const float*)d_in[2];  // [1] f32
    float* out = (float*)d_out;

    k_batch_centroid<<<BN, 256>>>(x);
    k_global_centroid<<<1, 1024>>>();
    k_stats<<<NBLK, 256>>>(x);
    k_reduce_partials<<<8, 256>>>();
    k_scale_kernel<<<1, 256>>>(gamma);
    k_output<<<NBLK, 256>>>(x, beta, out);
}

// round 2
// speedup vs baseline: 1.2723x; 1.2723x over previous
#include <cuda_runtime.h>
#include <math.h>

#define BN 128
#define SN 1024
#define DN 256
#define D4 64
#define NROWS (BN * SN)          // 131072
#define NBLK 1024                // blocks for the big row passes
#define ROWS_PER_BLK 128         // rows per block
#define RW 16                    // rows per warp

// ---------------- scratch (device globals; no allocation) ----------------
__device__ float g_pcb[NBLK * DN];     // per-block Euclidean partial sums (centroid pass)
__device__ float g_cb[BN * DN];        // per-batch centroids
__device__ float g_mu[DN];             // global centroid
__device__ float g_psum[NBLK * DN];    // per-block column sums of w
__device__ float g_psumsq[NBLK * DN];  // per-block column sums of w^2
__device__ float g_psum2[64 * DN];
__device__ float g_psumsq2[64 * DN];
__device__ float g_scale[DN];          // gamma / sqrt(var + eps)

// ---------------- helpers ----------------
__device__ __forceinline__ float wsum(float v) {
#pragma unroll
    for (int o = 16; o; o >>= 1) v += __shfl_xor_sync(0xffffffffu, v, o);
    return v;
}
// paired butterfly: two independent reductions, interleaved for ILP
__device__ __forceinline__ void wsum2(float& a, float& b) {
#pragma unroll
    for (int o = 16; o; o >>= 1) {
        a += __shfl_xor_sync(0xffffffffu, a, o);
        b += __shfl_xor_sync(0xffffffffu, b, o);
    }
}
__device__ __forceinline__ float4 f4z() { return make_float4(0.f, 0.f, 0.f, 0.f); }
__device__ __forceinline__ float4 f4add(float4 a, float4 b) {
    return make_float4(a.x + b.x, a.y + b.y, a.z + b.z, a.w + b.w);
}
__device__ __forceinline__ float4 f4scale(float4 a, float s) {
    return make_float4(a.x * s, a.y * s, a.z * s, a.w * s);
}
__device__ __forceinline__ float dot4(float4 a, float4 b) {
    return a.x * b.x + a.y * b.y + a.z * b.z + a.w * b.w;
}
__device__ __forceinline__ float4 wcomp(float4 xv, float4 muv, float alpha, float f, float coef) {
    float4 r;
    r.x = f * fmaf(-alpha, muv.x, xv.x) - coef * muv.x;
    r.y = f * fmaf(-alpha, muv.y, xv.y) - coef * muv.y;
    r.z = f * fmaf(-alpha, muv.z, xv.z) - coef * muv.z;
    r.w = f * fmaf(-alpha, muv.w, xv.w) - coef * muv.w;
    return r;
}
__device__ __forceinline__ float4 f4mul(float4 a, float4 b) {
    return make_float4(a.x * b.x, a.y * b.y, a.z * b.z, a.w * b.w);
}
__device__ __forceinline__ float4 f4fma(float4 a, float s, float4 b) {
    return make_float4(fmaf(a.x, s, b.x), fmaf(a.y, s, b.y), fmaf(a.z, s, b.z), fmaf(a.w, s, b.w));
}

// ---------------- kernel A: Euclidean partial sums (grid 1024) ----------------
// Block g covers 128 consecutive rows (batch b = g>>3). Sum rows -> g_pcb[g][:].
__global__ void __launch_bounds__(256) k_psum_batch(const float* __restrict__ x) {
    int g = blockIdx.x;
    int w = threadIdx.x >> 5, l = threadIdx.x & 31;
    const float4* xp = (const float4*)x + (size_t)g * ROWS_PER_BLK * D4;
    float4 a0 = f4z(), a1 = f4z();
#pragma unroll 4
    for (int i = 0; i < 16; i++) {
        const float4* row = xp + (size_t)(w + 8 * i) * D4;
        a0 = f4add(a0, row[l]);
        a1 = f4add(a1, row[l + 32]);
    }
    __shared__ float4 s0[8][32], s1[8][32];
    s0[w][l] = a0;
    s1[w][l] = a1;
    __syncthreads();
    if (w == 0) {
        float4 t = f4z();
#pragma unroll
        for (int i = 0; i < 8; i++) t = f4add(t, s0[i][l]);
        ((float4*)g_pcb)[g * D4 + l] = t;
    }
    if (w == 1) {
        float4 t = f4z();
#pragma unroll
        for (int i = 0; i < 8; i++) t = f4add(t, s1[i][l]);
        ((float4*)g_pcb)[g * D4 + 32 + l] = t;
    }
}

// ---------------- kernel B: per-batch centroid from 8 partials (grid 128) ----------------
__global__ void __launch_bounds__(64) k_batch_centroid2() {
    int b = blockIdx.x;
    int t = threadIdx.x;  // 0..63, one float4 column each
    const float4* p = (const float4*)g_pcb;
    float4 s = f4z();
#pragma unroll
    for (int e = 0; e < 8; e++) s = f4add(s, p[(b * 8 + e) * D4 + t]);
    float4 avg = f4scale(s, 1.0f / (float)SN);
    float part = (t == 0)
        ? (avg.x * avg.x - (avg.y * avg.y + avg.z * avg.z + avg.w * avg.w))
        : -dot4(avg, avg);
    part = wsum(part);
    __shared__ float sp[2];
    __shared__ float sr;
    if ((t & 31) == 0) sp[t >> 5] = part;
    __syncthreads();
    if (t == 0) sr = rsqrtf(fmaxf(fabsf(sp[0] + sp[1]), 1e-8f));
    __syncthreads();
    ((float4*)g_cb)[b * D4 + t] = f4scale(avg, sr);
}

// ---------------- kernel C: global centroid over batches (grid 1) ----------------
__global__ void k_global_centroid() {
    int tid = threadIdx.x;
    int q = tid >> 8, d = tid & 255;
    __shared__ float sm[4][DN];
    __shared__ float sm2[8];
    __shared__ float srden;
    float s = 0.f;
#pragma unroll 8
    for (int b = q * 32; b < q * 32 + 32; b++) s += g_cb[b * DN + d];
    sm[q][d] = s;
    __syncthreads();
    if (tid < DN) {
        float tot = sm[0][d] + sm[1][d] + sm[2][d] + sm[3][d];
        float avg = tot * (1.0f / (float)BN);
        sm[0][d] = avg;
        float part = (d == 0) ? avg * avg : -avg * avg;
        part = wsum(part);
        if ((tid & 31) == 0) sm2[tid >> 5] = part;
    }
    __syncthreads();
    if (tid == 0) {
        float nrm = 0.f;
#pragma unroll
        for (int i = 0; i < 8; i++) nrm += sm2[i];
        srden = rsqrtf(fmaxf(fabsf(nrm), 1e-8f));
    }
    __syncthreads();
    if (tid < DN) g_mu[d] = sm[0][d] * srden;
}

// ---------------- kernel D: tangent stats pass, dual-row ILP (grid 1024) ----------------
__global__ void __launch_bounds__(256) k_stats(const float* __restrict__ x) {
    int w = threadIdx.x >> 5, l = threadIdx.x & 31;
    const float4* mu4 = (const float4*)g_mu;
    float4 mu_a = mu4[l], mu_b = mu4[l + 32];
    float mu0 = g_mu[0];
    float inv1 = 1.0f / (1.0f + mu0);
    int rbase = blockIdx.x * ROWS_PER_BLK + w * RW;
    const float4* xp = (const float4*)x;

    float4 s1a = f4z(), s1b = f4z(), s2a = f4z(), s2b = f4z();
    float4 xa0 = xp[(size_t)rbase * D4 + l],        xb0 = xp[(size_t)rbase * D4 + 32 + l];
    float4 xa1 = xp[(size_t)(rbase + 1) * D4 + l],  xb1 = xp[(size_t)(rbase + 1) * D4 + 32 + l];
#pragma unroll
    for (int i = 0; i < RW / 2; i++) {
        float4 na0 = f4z(), nb0 = f4z(), na1 = f4z(), nb1 = f4z();
        if (i + 1 < RW / 2) {
            size_t nr = (size_t)(rbase + 2 * i + 2) * D4;
            na0 = xp[nr + l];       nb0 = xp[nr + 32 + l];
            na1 = xp[nr + D4 + l];  nb1 = xp[nr + D4 + 32 + l];
        }
        float part0 = -dot4(mu_b, xb0);
        part0 += (l == 0)
            ? (mu0 * xa0.x - (mu_a.y * xa0.y + mu_a.z * xa0.z + mu_a.w * xa0.w))
            : -dot4(mu_a, xa0);
        float part1 = -dot4(mu_b, xb1);
        part1 += (l == 0)
            ? (mu0 * xa1.x - (mu_a.y * xa1.y + mu_a.z * xa1.z + mu_a.w * xa1.w))
            : -dot4(mu_a, xa1);
        wsum2(part0, part1);
        float x00 = __shfl_sync(0xffffffffu, xa0.x, 0);
        float x01 = __shfl_sync(0xffffffffu, xa1.x, 0);

        float alpha0 = fmaxf(part0, 1.0f + 1e-7f);
        float alpha1 = fmaxf(part1, 1.0f + 1e-7f);
        float f0 = acoshf(alpha0) * rsqrtf(fmaf(alpha0, alpha0, -1.0f));
        float f1 = acoshf(alpha1) * rsqrtf(fmaf(alpha1, alpha1, -1.0f));
        float coef0 = f0 * fmaf(-alpha0, mu0, x00) * inv1;
        float coef1 = f1 * fmaf(-alpha1, mu0, x01) * inv1;
        float4 wa0 = wcomp(xa0, mu_a, alpha0, f0, coef0);
        float4 wb0 = wcomp(xb0, mu_b, alpha0, f0, coef0);
        float4 wa1 = wcomp(xa1, mu_a, alpha1, f1, coef1);
        float4 wb1 = wcomp(xb1, mu_b, alpha1, f1, coef1);
        if (l == 0) { wa0.x -= coef0; wa1.x -= coef1; }
        s1a = f4add(s1a, f4add(wa0, wa1));
        s1b = f4add(s1b, f4add(wb0, wb1));
        s2a = f4add(s2a, f4add(f4mul(wa0, wa0), f4mul(wa1, wa1)));
        s2b = f4add(s2b, f4add(f4mul(wb0, wb0), f4mul(wb1, wb1)));
        xa0 = na0; xb0 = nb0; xa1 = na1; xb1 = nb1;
    }
    // combine 8 warps -> per-block column partials
    __shared__ float4 sbA[8][32], sbB[8][32];
    sbA[w][l] = s1a;
    sbB[w][l] = s1b;
    __syncthreads();
    if (w == 0) {
        float4 t = f4z();
#pragma unroll
        for (int i = 0; i < 8; i++) t = f4add(t, sbA[i][l]);
        ((float4*)g_psum)[blockIdx.x * D4 + l] = t;
    }
    if (w == 1) {
        float4 t = f4z();
#pragma unroll
        for (int i = 0; i < 8; i++) t = f4add(t, sbB[i][l]);
        ((float4*)g_psum)[blockIdx.x * D4 + 32 + l] = t;
    }
    __syncthreads();
    sbA[w][l] = s2a;
    sbB[w][l] = s2b;
    __syncthreads();
    if (w == 0) {
        float4 t = f4z();
#pragma unroll
        for (int i = 0; i < 8; i++) t = f4add(t, sbA[i][l]);
        ((float4*)g_psumsq)[blockIdx.x * D4 + l] = t;
    }
    if (w == 1) {
        float4 t = f4z();
#pragma unroll
        for (int i = 0; i < 8; i++) t = f4add(t, sbB[i][l]);
        ((float4*)g_psumsq)[blockIdx.x * D4 + 32 + l] = t;
    }
}

// ---------------- kernel E: reduce 1024 partials -> 64 (grid 64) ----------------
__global__ void __launch_bounds__(256) k_reduce2() {
    int j = blockIdx.x, d = threadIdx.x;
    float s = 0.f, s2 = 0.f;
    int base = j * 16;
#pragma unroll
    for (int i = 0; i < 16; i++) {
        s += g_psum[(size_t)(base + i) * DN + d];
        s2 += g_psumsq[(size_t)(base + i) * DN + d];
    }
    g_psum2[j * DN + d] = s;
    g_psumsq2[j * DN + d] = s2;
}

// ---------------- kernel F: final variance -> scale (grid 1) ----------------
__global__ void __launch_bounds__(256) k_scale_kernel(const float* __restrict__ gamma) {
    int d = threadIdx.x;
    float s = 0.f, s2 = 0.f;
#pragma unroll
    for (int j = 0; j < 64; j++) {
        s += g_psum2[j * DN + d];
        s2 += g_psumsq2[j * DN + d];
    }
    float invN = 1.0f / (float)NROWS;
    float mean = s * invN;
    float var = fmaf(-mean, mean, s2 * invN);
    var = fmaxf(var, 0.0f);
    g_scale[d] = gamma[0] * rsqrtf(var + 1e-5f);
}

// ---------------- kernel G: output pass, dual-row ILP (grid 1024) ----------------
__global__ void __launch_bounds__(256) k_output(const float* __restrict__ x,
                                                const float* __restrict__ beta,
                                                float* __restrict__ out) {
    int w = threadIdx.x >> 5, l = threadIdx.x & 31;
    const float4* mu4 = (const float4*)g_mu;
    const float4* sc4 = (const float4*)g_scale;
    const float4* be4 = (const float4*)beta;
    float4 mu_a = mu4[l], mu_b = mu4[l + 32];
    float4 sc_a = sc4[l], sc_b = sc4[l + 32];
    float4 be_a = be4[l], be_b = be4[l + 32];
    float mu0 = g_mu[0];
    float inv1 = 1.0f / (1.0f + mu0);
    float beta0 = beta[0];
    float inv1b = 1.0f / (1.0f + beta0);
    int rbase = blockIdx.x * ROWS_PER_BLK + w * RW;
    const float4* xp = (const float4*)x;
    float4* op = (float4*)out;

    float4 xa0 = xp[(size_t)rbase * D4 + l],        xb0 = xp[(size_t)rbase * D4 + 32 + l];
    float4 xa1 = xp[(size_t)(rbase + 1) * D4 + l],  xb1 = xp[(size_t)(rbase + 1) * D4 + 32 + l];
#pragma unroll
    for (int i = 0; i < RW / 2; i++) {
        int r = rbase + 2 * i;
        float4 na0 = f4z(), nb0 = f4z(), na1 = f4z(), nb1 = f4z();
        if (i + 1 < RW / 2) {
            size_t nr = (size_t)(r + 2) * D4;
            na0 = xp[nr + l];       nb0 = xp[nr + 32 + l];
            na1 = xp[nr + D4 + l];  nb1 = xp[nr + D4 + 32 + l];
        }
        // ---- stage 1: alpha ----
        float part0 = -dot4(mu_b, xb0);
        part0 += (l == 0)
            ? (mu0 * xa0.x - (mu_a.y * xa0.y + mu_a.z * xa0.z + mu_a.w * xa0.w))
            : -dot4(mu_a, xa0);
        float part1 = -dot4(mu_b, xb1);
        part1 += (l == 0)
            ? (mu0 * xa1.x - (mu_a.y * xa1.y + mu_a.z * xa1.z + mu_a.w * xa1.w))
            : -dot4(mu_a, xa1);
        wsum2(part0, part1);
        float x00 = __shfl_sync(0xffffffffu, xa0.x, 0);
        float x01 = __shfl_sync(0xffffffffu, xa1.x, 0);
        float alpha0 = fmaxf(part0, 1.0f + 1e-7f);
        float alpha1 = fmaxf(part1, 1.0f + 1e-7f);
        float f0 = acoshf(alpha0) * rsqrtf(fmaf(alpha0, alpha0, -1.0f));
        float f1 = acoshf(alpha1) * rsqrtf(fmaf(alpha1, alpha1, -1.0f));
        float coef0 = f0 * fmaf(-alpha0, mu0, x00) * inv1;
        float coef1 = f1 * fmaf(-alpha1, mu0, x01) * inv1;
        float4 wa0 = wcomp(xa0, mu_a, alpha0, f0, coef0);
        float4 wb0 = wcomp(xb0, mu_b, alpha0, f0, coef0);
        float4 wa1 = wcomp(xa1, mu_a, alpha1, f1, coef1);
        float4 wb1 = wcomp(xb1, mu_b, alpha1, f1, coef1);
        if (l == 0) { wa0.x -= coef0; wa1.x -= coef1; }
        // ---- scale ----
        float4 va0 = f4mul(wa0, sc_a), vb0 = f4mul(wb0, sc_b);
        float4 va1 = f4mul(wa1, sc_a), vb1 = f4mul(wb1, sc_b);
        // ---- stage 2: transp0(beta, v) ----
        float p20 = dot4(be_b, vb0);
        p20 += (l == 0)
            ? (-beta0 * va0.x + be_a.y * va0.y + be_a.z * va0.z + be_a.w * va0.w)
            : dot4(be_a, va0);
        float p21 = dot4(be_b, vb1);
        p21 += (l == 0)
            ? (-beta0 * va1.x + be_a.y * va1.y + be_a.z * va1.z + be_a.w * va1.w)
            : dot4(be_a, va1);
        wsum2(p20, p21);
        float c20 = p20 * inv1b, c21 = p21 * inv1b;
        float4 ya0 = f4fma(be_a, c20, va0), yb0 = f4fma(be_b, c20, vb0);
        float4 ya1 = f4fma(be_a, c21, va1), yb1 = f4fma(be_b, c21, vb1);
        if (l == 0) { ya0.x += c20; ya1.x += c21; }
        // ---- stage 3: expmap(beta, y) ----
        float p30 = dot4(yb0, yb0);
        p30 += (l == 0)
            ? (-ya0.x * ya0.x + ya0.y * ya0.y + ya0.z * ya0.z + ya0.w * ya0.w)
            : dot4(ya0, ya0);
        float p31 = dot4(yb1, yb1);
        p31 += (l == 0)
            ? (-ya1.x * ya1.x + ya1.y * ya1.y + ya1.z * ya1.z + ya1.w * ya1.w)
            : dot4(ya1, ya1);
        wsum2(p30, p31);
        float n0 = sqrtf(fmaxf(p30, 1e-7f));
        float n1 = sqrtf(fmaxf(p31, 1e-7f));
        float ch0 = coshf(n0), sn0 = sinhf(n0) / n0;
        float ch1 = coshf(n1), sn1 = sinhf(n1) / n1;
        float4 oa0 = f4fma(be_a, ch0, f4scale(ya0, sn0));
        float4 ob0 = f4fma(be_b, ch0, f4scale(yb0, sn0));
        float4 oa1 = f4fma(be_a, ch1, f4scale(ya1, sn1));
        float4 ob1 = f4fma(be_b, ch1, f4scale(yb1, sn1));
        __stcs(op + (size_t)r * D4 + l, oa0);
        __stcs(op + (size_t)r * D4 + 32 + l, ob0);
        __stcs(op + (size_t)(r + 1) * D4 + l, oa1);
        __stcs(op + (size_t)(r + 1) * D4 + 32 + l, ob1);
        xa0 = na0; xb0 = nb0; xa1 = na1; xb1 = nb1;
    }
}

// ---------------- launcher ----------------
extern "C" void kernel_launch(void* const* d_in, const int* in_sizes, int n_in,
                              void* d_out, int out_size) {
    const float* x = (const float*)d_in[0];      // [B,S,D] f32
    const float* beta = (const float*)d_in[1];   // [D] f32
    const float* gamma = (const float*)d_in[2];  // [1] f32
    float* out = (float*)d_out;

    k_psum_batch<<<NBLK, 256>>>(x);
    k_batch_centroid2<<<BN, 64>>>();
    k_global_centroid<<<1, 1024>>>();
    k_stats<<<NBLK, 256>>>(x);
    k_reduce2<<<64, 256>>>();
    k_scale_kernel<<<1, 256>>>(gamma);
    k_output<<<NBLK, 256>>>(x, beta, out);
}

// round 5
// speedup vs baseline: 1.3548x; 1.0649x over previous
#include <cuda_runtime.h>
#include <math.h>

#define BN 128
#define SN 1024
#define DN 256
#define D4 64
#define NROWS (BN * SN)          // 131072
#define NBLK 1024                // blocks for the big row passes
#define ROWS_PER_BLK 128         // rows per block
#define RW 16                    // rows per warp

// ---------------- scratch (device globals; no allocation) ----------------
__device__ float g_pcb[NBLK * DN];     // per-block Euclidean partial sums (centroid pass)
__device__ float g_cb[BN * DN];        // per-batch centroids
__device__ float g_mu[DN];             // global centroid
__device__ float g_psum[NBLK * DN];    // per-block column sums of w
__device__ float g_psumsq[NBLK * DN];  // per-block column sums of w^2
__device__ float g_psum2[64 * DN];
__device__ float g_psumsq2[64 * DN];
__device__ float g_scale[DN];          // gamma / sqrt(var + eps)

// ---------------- helpers ----------------
__device__ __forceinline__ float wsum(float v) {
#pragma unroll
    for (int o = 16; o; o >>= 1) v += __shfl_xor_sync(0xffffffffu, v, o);
    return v;
}
__device__ __forceinline__ void wsum2(float& a, float& b) {
#pragma unroll
    for (int o = 16; o; o >>= 1) {
        a += __shfl_xor_sync(0xffffffffu, a, o);
        b += __shfl_xor_sync(0xffffffffu, b, o);
    }
}
__device__ __forceinline__ void wsum4(float& a, float& b, float& c, float& d) {
#pragma unroll
    for (int o = 16; o; o >>= 1) {
        a += __shfl_xor_sync(0xffffffffu, a, o);
        b += __shfl_xor_sync(0xffffffffu, b, o);
        c += __shfl_xor_sync(0xffffffffu, c, o);
        d += __shfl_xor_sync(0xffffffffu, d, o);
    }
}
__device__ __forceinline__ float4 f4z() { return make_float4(0.f, 0.f, 0.f, 0.f); }
__device__ __forceinline__ float4 f4add(float4 a, float4 b) {
    return make_float4(a.x + b.x, a.y + b.y, a.z + b.z, a.w + b.w);
}
__device__ __forceinline__ float4 f4scale(float4 a, float s) {
    return make_float4(a.x * s, a.y * s, a.z * s, a.w * s);
}
__device__ __forceinline__ float dot4(float4 a, float4 b) {
    return a.x * b.x + a.y * b.y + a.z * b.z + a.w * b.w;
}
__device__ __forceinline__ float4 wcomp(float4 xv, float4 muv, float alpha, float f, float coef) {
    float4 r;
    r.x = f * fmaf(-alpha, muv.x, xv.x) - coef * muv.x;
    r.y = f * fmaf(-alpha, muv.y, xv.y) - coef * muv.y;
    r.z = f * fmaf(-alpha, muv.z, xv.z) - coef * muv.z;
    r.w = f * fmaf(-alpha, muv.w, xv.w) - coef * muv.w;
    return r;
}
__device__ __forceinline__ float4 f4mul(float4 a, float4 b) {
    return make_float4(a.x * b.x, a.y * b.y, a.z * b.z, a.w * b.w);
}
__device__ __forceinline__ float4 f4fma(float4 a, float s, float4 b) {
    return make_float4(fmaf(a.x, s, b.x), fmaf(a.y, s, b.y), fmaf(a.z, s, b.z), fmaf(a.w, s, b.w));
}

// ---------------- kernel A: Euclidean partial sums (grid 1024, FORWARD) ----------------
__global__ void __launch_bounds__(256) k_psum_batch(const float* __restrict__ x) {
    int g = blockIdx.x;
    int w = threadIdx.x >> 5, l = threadIdx.x & 31;
    const float4* xp = (const float4*)x + (size_t)g * ROWS_PER_BLK * D4;
    float4 a0 = f4z(), a1 = f4z();
#pragma unroll 4
    for (int i = 0; i < 16; i++) {
        const float4* row = xp + (size_t)(w + 8 * i) * D4;
        a0 = f4add(a0, row[l]);
        a1 = f4add(a1, row[l + 32]);
    }
    __shared__ float4 s0[8][32], s1[8][32];
    s0[w][l] = a0;
    s1[w][l] = a1;
    __syncthreads();
    if (w == 0) {
        float4 t = f4z();
#pragma unroll
        for (int i = 0; i < 8; i++) t = f4add(t, s0[i][l]);
        ((float4*)g_pcb)[g * D4 + l] = t;
    }
    if (w == 1) {
        float4 t = f4z();
#pragma unroll
        for (int i = 0; i < 8; i++) t = f4add(t, s1[i][l]);
        ((float4*)g_pcb)[g * D4 + 32 + l] = t;
    }
}

// ---------------- kernel B: per-batch centroid from 8 partials (grid 128) ----------------
__global__ void __launch_bounds__(64) k_batch_centroid2() {
    int b = blockIdx.x;
    int t = threadIdx.x;  // 0..63
    const float4* p = (const float4*)g_pcb;
    float4 s = f4z();
#pragma unroll
    for (int e = 0; e < 8; e++) s = f4add(s, p[(b * 8 + e) * D4 + t]);
    float4 avg = f4scale(s, 1.0f / (float)SN);
    float part = (t == 0)
        ? (avg.x * avg.x - (avg.y * avg.y + avg.z * avg.z + avg.w * avg.w))
        : -dot4(avg, avg);
    part = wsum(part);
    __shared__ float sp[2];
    __shared__ float sr;
    if ((t & 31) == 0) sp[t >> 5] = part;
    __syncthreads();
    if (t == 0) sr = rsqrtf(fmaxf(fabsf(sp[0] + sp[1]), 1e-8f));
    __syncthreads();
    ((float4*)g_cb)[b * D4 + t] = f4scale(avg, sr);
}

// ---------------- kernel C: global centroid over batches (grid 1) ----------------
__global__ void k_global_centroid() {
    int tid = threadIdx.x;
    int q = tid >> 8, d = tid & 255;
    __shared__ float sm[4][DN];
    __shared__ float sm2[8];
    __shared__ float srden;
    float s = 0.f;
#pragma unroll 8
    for (int b = q * 32; b < q * 32 + 32; b++) s += g_cb[b * DN + d];
    sm[q][d] = s;
    __syncthreads();
    if (tid < DN) {
        float tot = sm[0][d] + sm[1][d] + sm[2][d] + sm[3][d];
        float avg = tot * (1.0f / (float)BN);
        sm[0][d] = avg;
        float part = (d == 0) ? avg * avg : -avg * avg;
        part = wsum(part);
        if ((tid & 31) == 0) sm2[tid >> 5] = part;
    }
    __syncthreads();
    if (tid == 0) {
        float nrm = 0.f;
#pragma unroll
        for (int i = 0; i < 8; i++) nrm += sm2[i];
        srden = rsqrtf(fmaxf(fabsf(nrm), 1e-8f));
    }
    __syncthreads();
    if (tid < DN) g_mu[d] = sm[0][d] * srden;
}

// ---------------- kernel D: tangent stats pass (grid 1024, REVERSE order) ----------------
__global__ void __launch_bounds__(256, 4) k_stats(const float* __restrict__ x) {
    int g = (NBLK - 1) - blockIdx.x;  // reverse traversal: LRU-friendly vs pass 1
    int w = threadIdx.x >> 5, l = threadIdx.x & 31;
    const float4* mu4 = (const float4*)g_mu;
    float4 mu_a = mu4[l], mu_b = mu4[l + 32];
    float mu0 = g_mu[0];
    float inv1 = 1.0f / (1.0f + mu0);
    int rbase = g * ROWS_PER_BLK + w * RW;
    const float4* xp = (const float4*)x;

    float4 s1a = f4z(), s1b = f4z(), s2a = f4z(), s2b = f4z();
#pragma unroll
    for (int i = 0; i < RW / 2; i++) {
        size_t r0 = (size_t)(rbase + 2 * i) * D4;
        float4 xa0 = xp[r0 + l],      xb0 = xp[r0 + 32 + l];
        float4 xa1 = xp[r0 + D4 + l], xb1 = xp[r0 + D4 + 32 + l];
        float part0 = -dot4(mu_b, xb0);
        part0 += (l == 0)
            ? (mu0 * xa0.x - (mu_a.y * xa0.y + mu_a.z * xa0.z + mu_a.w * xa0.w))
            : -dot4(mu_a, xa0);
        float part1 = -dot4(mu_b, xb1);
        part1 += (l == 0)
            ? (mu0 * xa1.x - (mu_a.y * xa1.y + mu_a.z * xa1.z + mu_a.w * xa1.w))
            : -dot4(mu_a, xa1);
        wsum2(part0, part1);
        float x00 = __shfl_sync(0xffffffffu, xa0.x, 0);
        float x01 = __shfl_sync(0xffffffffu, xa1.x, 0);

        float alpha0 = fmaxf(part0, 1.0f + 1e-7f);
        float alpha1 = fmaxf(part1, 1.0f + 1e-7f);
        float f0 = acoshf(alpha0) * rsqrtf(fmaf(alpha0, alpha0, -1.0f));
        float f1 = acoshf(alpha1) * rsqrtf(fmaf(alpha1, alpha1, -1.0f));
        float coef0 = f0 * fmaf(-alpha0, mu0, x00) * inv1;
        float coef1 = f1 * fmaf(-alpha1, mu0, x01) * inv1;
        float4 wa0 = wcomp(xa0, mu_a, alpha0, f0, coef0);
        float4 wb0 = wcomp(xb0, mu_b, alpha0, f0, coef0);
        float4 wa1 = wcomp(xa1, mu_a, alpha1, f1, coef1);
        float4 wb1 = wcomp(xb1, mu_b, alpha1, f1, coef1);
        if (l == 0) { wa0.x -= coef0; wa1.x -= coef1; }
        s1a = f4add(s1a, f4add(wa0, wa1));
        s1b = f4add(s1b, f4add(wb0, wb1));
        s2a = f4add(s2a, f4add(f4mul(wa0, wa0), f4mul(wa1, wa1)));
        s2b = f4add(s2b, f4add(f4mul(wb0, wb0), f4mul(wb1, wb1)));
    }
    __shared__ float4 sbA[8][32], sbB[8][32];
    sbA[w][l] = s1a;
    sbB[w][l] = s1b;
    __syncthreads();
    if (w == 0) {
        float4 t = f4z();
#pragma unroll
        for (int i = 0; i < 8; i++) t = f4add(t, sbA[i][l]);
        ((float4*)g_psum)[g * D4 + l] = t;
    }
    if (w == 1) {
        float4 t = f4z();
#pragma unroll
        for (int i = 0; i < 8; i++) t = f4add(t, sbB[i][l]);
        ((float4*)g_psum)[g * D4 + 32 + l] = t;
    }
    __syncthreads();
    sbA[w][l] = s2a;
    sbB[w][l] = s2b;
    __syncthreads();
    if (w == 0) {
        float4 t = f4z();
#pragma unroll
        for (int i = 0; i < 8; i++) t = f4add(t, sbA[i][l]);
        ((float4*)g_psumsq)[g * D4 + l] = t;
    }
    if (w == 1) {
        float4 t = f4z();
#pragma unroll
        for (int i = 0; i < 8; i++) t = f4add(t, sbB[i][l]);
        ((float4*)g_psumsq)[g * D4 + 32 + l] = t;
    }
}

// ---------------- kernel E: reduce 1024 partials -> 64 (grid 64) ----------------
__global__ void __launch_bounds__(256) k_reduce2() {
    int j = blockIdx.x, d = threadIdx.x;
    float s = 0.f, s2 = 0.f;
    int base = j * 16;
#pragma unroll
    for (int i = 0; i < 16; i++) {
        s += g_psum[(size_t)(base + i) * DN + d];
        s2 += g_psumsq[(size_t)(base + i) * DN + d];
    }
    g_psum2[j * DN + d] = s;
    g_psumsq2[j * DN + d] = s2;
}

// ---------------- kernel F: final variance -> scale (grid 1) ----------------
__global__ void __launch_bounds__(256) k_scale_kernel(const float* __restrict__ gamma) {
    int d = threadIdx.x;
    float s = 0.f, s2 = 0.f;
#pragma unroll
    for (int j = 0; j < 64; j++) {
        s += g_psum2[j * DN + d];
        s2 += g_psumsq2[j * DN + d];
    }
    float invN = 1.0f / (float)NROWS;
    float mean = s * invN;
    float var = fmaf(-mean, mean, s2 * invN);
    var = fmaxf(var, 0.0f);
    g_scale[d] = gamma[0] * rsqrtf(var + 1e-5f);
}

// ---------------- kernel G: output pass (grid 1024, FORWARD) ----------------
// Fused reduction: Q(y) = Q(v) + 2*c2*(dotb - v0) + c2^2*Qa, so transp0-dot and
// expmap-norm collapse into ONE paired butterfly per row.
__global__ void __launch_bounds__(256, 4) k_output(const float* __restrict__ x,
                                                   const float* __restrict__ beta,
                                                   float* __restrict__ out) {
    int g = blockIdx.x;
    int w = threadIdx.x >> 5, l = threadIdx.x & 31;
    const float4* mu4 = (const float4*)g_mu;
    const float4* sc4 = (const float4*)g_scale;
    const float4* be4 = (const float4*)beta;
    float4 mu_a = mu4[l], mu_b = mu4[l + 32];
    float4 sc_a = sc4[l], sc_b = sc4[l + 32];
    float4 be_a = be4[l], be_b = be4[l + 32];
    float mu0 = g_mu[0];
    float inv1 = 1.0f / (1.0f + mu0);
    float beta0 = beta[0];
    float inv1b = 1.0f / (1.0f + beta0);
    // Qa = Q(add_origin(beta)) : per-kernel constant, one reduction at start
    float qa_part = dot4(be_b, be_b);
    qa_part += (l == 0)
        ? (-(1.0f + be_a.x) * (1.0f + be_a.x) + be_a.y * be_a.y + be_a.z * be_a.z + be_a.w * be_a.w)
        : dot4(be_a, be_a);
    float Qa = wsum(qa_part);

    int rbase = g * ROWS_PER_BLK + w * RW;
    const float4* xp = (const float4*)x;
    float4* op = (float4*)out;

#pragma unroll
    for (int i = 0; i < RW / 2; i++) {
        int r = rbase + 2 * i;
        size_t r0 = (size_t)r * D4;
        float4 xa0 = xp[r0 + l],      xb0 = xp[r0 + 32 + l];
        float4 xa1 = xp[r0 + D4 + l], xb1 = xp[r0 + D4 + 32 + l];
        // ---- stage 1: alpha ----
        float part0 = -dot4(mu_b, xb0);
        part0 += (l == 0)
            ? (mu0 * xa0.x - (mu_a.y * xa0.y + mu_a.z * xa0.z + mu_a.w * xa0.w))
            : -dot4(mu_a, xa0);
        float part1 = -dot4(mu_b, xb1);
        part1 += (l == 0)
            ? (mu0 * xa1.x - (mu_a.y * xa1.y + mu_a.z * xa1.z + mu_a.w * xa1.w))
            : -dot4(mu_a, xa1);
        wsum2(part0, part1);
        float x00 = __shfl_sync(0xffffffffu, xa0.x, 0);
        float x01 = __shfl_sync(0xffffffffu, xa1.x, 0);
        float alpha0 = fmaxf(part0, 1.0f + 1e-7f);
        float alpha1 = fmaxf(part1, 1.0f + 1e-7f);
        float f0 = acoshf(alpha0) * rsqrtf(fmaf(alpha0, alpha0, -1.0f));
        float f1 = acoshf(alpha1) * rsqrtf(fmaf(alpha1, alpha1, -1.0f));
        float coef0 = f0 * fmaf(-alpha0, mu0, x00) * inv1;
        float coef1 = f1 * fmaf(-alpha1, mu0, x01) * inv1;
        float4 wa0 = wcomp(xa0, mu_a, alpha0, f0, coef0);
        float4 wb0 = wcomp(xb0, mu_b, alpha0, f0, coef0);
        float4 wa1 = wcomp(xa1, mu_a, alpha1, f1, coef1);
        float4 wb1 = wcomp(xb1, mu_b, alpha1, f1, coef1);
        if (l == 0) { wa0.x -= coef0; wa1.x -= coef1; }
        // ---- scale ----
        float4 va0 = f4mul(wa0, sc_a), vb0 = f4mul(wb0, sc_b);
        float4 va1 = f4mul(wa1, sc_a), vb1 = f4mul(wb1, sc_b);
        // ---- stage 2 (fused): dotb = <beta,v>_L and Qv = Q(v), one butterfly ----
        float db0 = dot4(be_b, vb0);
        db0 += (l == 0)
            ? (-beta0 * va0.x + be_a.y * va0.y + be_a.z * va0.z + be_a.w * va0.w)
            : dot4(be_a, va0);
        float db1 = dot4(be_b, vb1);
        db1 += (l == 0)
            ? (-beta0 * va1.x + be_a.y * va1.y + be_a.z * va1.z + be_a.w * va1.w)
            : dot4(be_a, va1);
        float qv0 = dot4(vb0, vb0);
        qv0 += (l == 0)
            ? (-va0.x * va0.x + va0.y * va0.y + va0.z * va0.z + va0.w * va0.w)
            : dot4(va0, va0);
        float qv1 = dot4(vb1, vb1);
        qv1 += (l == 0)
            ? (-va1.x * va1.x + va1.y * va1.y + va1.z * va1.z + va1.w * va1.w)
            : dot4(va1, va1);
        wsum4(db0, qv0, db1, qv1);
        float v00 = __shfl_sync(0xffffffffu, va0.x, 0);
        float v01 = __shfl_sync(0xffffffffu, va1.x, 0);
        float c20 = db0 * inv1b, c21 = db1 * inv1b;
        float p30 = qv0 + 2.f * c20 * (db0 - v00) + c20 * c20 * Qa;
        float p31 = qv1 + 2.f * c21 * (db1 - v01) + c21 * c21 * Qa;
        float n0 = sqrtf(fmaxf(p30, 1e-7f));
        float n1 = sqrtf(fmaxf(p31, 1e-7f));
        float ch0 = coshf(n0), sn0 = sinhf(n0) / n0;
        float ch1 = coshf(n1), sn1 = sinhf(n1) / n1;
        // y = v + c2*add_origin(beta); out = ch*beta + sn*y
        float4 ya0 = f4fma(be_a, c20, va0), yb0 = f4fma(be_b, c20, vb0);
        float4 ya1 = f4fma(be_a, c21, va1), yb1 = f4fma(be_b, c21, vb1);
        if (l == 0) { ya0.x += c20; ya1.x += c21; }
        float4 oa0 = f4fma(be_a, ch0, f4scale(ya0, sn0));
        float4 ob0 = f4fma(be_b, ch0, f4scale(yb0, sn0));
        float4 oa1 = f4fma(be_a, ch1, f4scale(ya1, sn1));
        float4 ob1 = f4fma(be_b, ch1, f4scale(yb1, sn1));
        __stcs(op + r0 + l, oa0);
        __stcs(op + r0 + 32 + l, ob0);
        __stcs(op + r0 + D4 + l, oa1);
        __stcs(op + r0 + D4 + 32 + l, ob1);
    }
}

// ---------------- launcher ----------------
extern "C" void kernel_launch(void* const* d_in, const int* in_sizes, int n_in,
                              void* d_out, int out_size) {
    const float* x = (const float*)d_in[0];      // [B,S,D] f32
    const float* beta = (const float*)d_in[1];   // [D] f32
    const float* gamma = (const float*)d_in[2];  // [1] f32
    float* out = (float*)d_out;

    k_psum_batch<<<NBLK, 256>>>(x);
    k_batch_centroid2<<<BN, 64>>>();
    k_global_centroid<<<1, 1024>>>();
    k_stats<<<NBLK, 256>>>(x);
    k_reduce2<<<64, 256>>>();
    k_scale_kernel<<<1, 256>>>(gamma);
    k_output<<<NBLK, 256>>>(x, beta, out);
}